// round 1
// baseline (speedup 1.0000x reference)
#include <cuda_runtime.h>
#include <math.h>

#define B_    16
#define HH_   48
#define WW_   48
#define N_    2304
#define C_    384
#define C2_   768
#define NH_   8
#define DD_   48
#define ROWS_ 36864

// ---------------- scratch (device globals; no allocation allowed) ----------------
__device__ float g_xn  [(size_t)ROWS_ * C_];        // LN output (reused 3x)
__device__ float g_qkvT[(size_t)3 * B_ * C_ * N_];  // [s][b][cc][n]
__device__ float g_rn  [2 * B_ * C_];               // reciprocal L2 norms for q,k
__device__ float g_attn[B_ * NH_ * DD_ * DD_];      // softmax matrices
__device__ float g_onc [(size_t)ROWS_ * C_];        // attention out, [B,N,C]
__device__ float g_x1  [(size_t)ROWS_ * C_];
__device__ float g_hid [(size_t)ROWS_ * C2_];
__device__ float g_x2  [(size_t)ROWS_ * C_];
__device__ float g_c1  [(size_t)ROWS_ * C_];
__device__ float g_wt1 [9 * C_ * C_];               // conv weights [tap][o][ci]
__device__ float g_wt2 [9 * C_ * C_];

__device__ __forceinline__ float gelu_f(float v) {
    return 0.5f * v * (1.0f + erff(v * 0.70710678118654752440f));
}

// ---------------- LayerNorm: one 128-thread block per row of 384 ----------------
__global__ void ln_kernel(const float* __restrict__ in, const float* __restrict__ g,
                          const float* __restrict__ b, float* __restrict__ outp)
{
    const int r = blockIdx.x;
    const int t = threadIdx.x;
    const float* row = in + (size_t)r * C_;
    float v0 = row[t], v1 = row[t + 128], v2 = row[t + 256];
    float s = v0 + v1 + v2;
    float ss = v0 * v0 + v1 * v1 + v2 * v2;
    for (int o = 16; o; o >>= 1) {
        s  += __shfl_down_sync(0xffffffffu, s,  o);
        ss += __shfl_down_sync(0xffffffffu, ss, o);
    }
    __shared__ float sh[8];
    if ((t & 31) == 0) { sh[t >> 5] = s; sh[4 + (t >> 5)] = ss; }
    __syncthreads();
    if (t == 0) {
        float S  = sh[0] + sh[1] + sh[2] + sh[3];
        float SS = sh[4] + sh[5] + sh[6] + sh[7];
        float mean = S * (1.0f / C_);
        float var  = SS * (1.0f / C_) - mean * mean;
        sh[0] = mean;
        sh[1] = rsqrtf(var + 1e-5f);
    }
    __syncthreads();
    float mean = sh[0], rstd = sh[1];
    float* orow = outp + (size_t)r * C_;
    orow[t]       = (v0 - mean) * rstd * g[t]       + b[t];
    orow[t + 128] = (v1 - mean) * rstd * g[t + 128] + b[t + 128];
    orow[t + 256] = (v2 - mean) * rstd * g[t + 256] + b[t + 256];
}

// ---------------- shared GEMM epilogue ----------------
// EPI 0: scatter into g_qkvT      (out = qkvT)
// EPI 1: out = e4 + e5 * acc                       (residual; proj & conv2)
// EPI 2: out = gelu(bn(acc)) with bn = e0..e3      (mlp1 & conv1)
// EPI 3: out = e4 + e5 * bn(acc)                   (mlp2)
template <int EPI>
__device__ __forceinline__ void do_epilogue(
    float (&acc)[8][4], int m0, int n0, int tx, int ty, int ldo,
    const float* __restrict__ e0, const float* __restrict__ e1,
    const float* __restrict__ e2, const float* __restrict__ e3,
    const float* __restrict__ e4, const float* __restrict__ e5,
    float* __restrict__ out)
{
    if (EPI == 0) {
        const int b   = m0 / N_;
        const int n00 = (m0 % N_) + ty * 8;
#pragma unroll
        for (int j = 0; j < 4; j++) {
            int r  = n0 + tx * 4 + j;
            int s  = r / C_;
            int cc = r - s * C_;
            float* dst = out + ((size_t)(s * B_ + b) * C_ + cc) * (size_t)N_ + n00;
            *(float4*)dst       = make_float4(acc[0][j], acc[1][j], acc[2][j], acc[3][j]);
            *(float4*)(dst + 4) = make_float4(acc[4][j], acc[5][j], acc[6][j], acc[7][j]);
        }
        return;
    }
    const int cb = n0 + tx * 4;
    float4 sc = make_float4(1.f, 1.f, 1.f, 1.f);
    float4 bi = make_float4(0.f, 0.f, 0.f, 0.f);
    float4 gm = make_float4(0.f, 0.f, 0.f, 0.f);
    if (EPI == 2 || EPI == 3) {
        float s0 = e0[cb + 0] * rsqrtf(e3[cb + 0] + 1e-5f);
        float s1 = e0[cb + 1] * rsqrtf(e3[cb + 1] + 1e-5f);
        float s2 = e0[cb + 2] * rsqrtf(e3[cb + 2] + 1e-5f);
        float s3 = e0[cb + 3] * rsqrtf(e3[cb + 3] + 1e-5f);
        sc = make_float4(s0, s1, s2, s3);
        bi = make_float4(e1[cb + 0] - e2[cb + 0] * s0, e1[cb + 1] - e2[cb + 1] * s1,
                         e1[cb + 2] - e2[cb + 2] * s2, e1[cb + 3] - e2[cb + 3] * s3);
    }
    if (EPI == 1 || EPI == 3) gm = *(const float4*)&e5[cb];
#pragma unroll
    for (int i = 0; i < 8; i++) {
        size_t off = (size_t)(m0 + ty * 8 + i) * ldo + cb;
        float4 v = make_float4(acc[i][0], acc[i][1], acc[i][2], acc[i][3]);
        if (EPI == 1) {
            float4 xr = *(const float4*)&e4[off];
            v = make_float4(xr.x + gm.x * v.x, xr.y + gm.y * v.y,
                            xr.z + gm.z * v.z, xr.w + gm.w * v.w);
        } else if (EPI == 2) {
            v = make_float4(gelu_f(v.x * sc.x + bi.x), gelu_f(v.y * sc.y + bi.y),
                            gelu_f(v.z * sc.z + bi.z), gelu_f(v.w * sc.w + bi.w));
        } else if (EPI == 3) {
            float4 xr = *(const float4*)&e4[off];
            v = make_float4(xr.x + gm.x * (v.x * sc.x + bi.x),
                            xr.y + gm.y * (v.y * sc.y + bi.y),
                            xr.z + gm.z * (v.z * sc.z + bi.z),
                            xr.w + gm.w * (v.w * sc.w + bi.w));
        }
        *(float4*)&out[off] = v;
    }
}

// ---------------- NT GEMM: C[m][n] = sum_k A[m][k]*Bw[n][k]; 128x64x16 tile ----------------
template <int EPI>
__global__ void __launch_bounds__(256) gemm_nt(
    const float* __restrict__ A, const float* __restrict__ Bw, int K, int ldo,
    const float* __restrict__ e0, const float* __restrict__ e1,
    const float* __restrict__ e2, const float* __restrict__ e3,
    const float* __restrict__ e4, const float* __restrict__ e5,
    float* __restrict__ out)
{
    __shared__ float As[16][132];
    __shared__ float Bs[16][68];
    const int t  = threadIdx.x;
    const int m0 = blockIdx.x * 128;
    const int n0 = blockIdx.y * 64;
    const int tx = t & 15, ty = t >> 4;
    const int ar = t >> 2, kq = (t & 3) * 4;

    float acc[8][4];
#pragma unroll
    for (int i = 0; i < 8; i++)
#pragma unroll
        for (int j = 0; j < 4; j++) acc[i][j] = 0.f;

    const float* Ap0 = A  + (size_t)(m0 + ar)      * K + kq;
    const float* Ap1 = A  + (size_t)(m0 + ar + 64) * K + kq;
    const float* Bp  = Bw + (size_t)(n0 + ar)      * K + kq;

    for (int kt = 0; kt < K; kt += 16) {
        float4 a0 = *(const float4*)(Ap0 + kt);
        float4 a1 = *(const float4*)(Ap1 + kt);
        float4 bv = *(const float4*)(Bp  + kt);
        __syncthreads();
        As[kq + 0][ar] = a0.x; As[kq + 1][ar] = a0.y; As[kq + 2][ar] = a0.z; As[kq + 3][ar] = a0.w;
        As[kq + 0][ar + 64] = a1.x; As[kq + 1][ar + 64] = a1.y;
        As[kq + 2][ar + 64] = a1.z; As[kq + 3][ar + 64] = a1.w;
        Bs[kq + 0][ar] = bv.x; Bs[kq + 1][ar] = bv.y; Bs[kq + 2][ar] = bv.z; Bs[kq + 3][ar] = bv.w;
        __syncthreads();
#pragma unroll
        for (int k = 0; k < 16; k++) {
            float4 x0 = *(const float4*)&As[k][ty * 8];
            float4 x1 = *(const float4*)&As[k][ty * 8 + 4];
            float4 y  = *(const float4*)&Bs[k][tx * 4];
            float am[8] = {x0.x, x0.y, x0.z, x0.w, x1.x, x1.y, x1.z, x1.w};
            float bm[4] = {y.x, y.y, y.z, y.w};
#pragma unroll
            for (int i = 0; i < 8; i++)
#pragma unroll
                for (int j = 0; j < 4; j++) acc[i][j] = fmaf(am[i], bm[j], acc[i][j]);
        }
    }
    do_epilogue<EPI>(acc, m0, n0, tx, ty, ldo, e0, e1, e2, e3, e4, e5, out);
}

// ---------------- 3x3 conv as 9 shifted NT GEMMs (channels-last) ----------------
template <int EPI>
__global__ void __launch_bounds__(256) conv_gemm(
    const float* __restrict__ A, const float* __restrict__ Wt,
    const float* __restrict__ e0, const float* __restrict__ e1,
    const float* __restrict__ e2, const float* __restrict__ e3,
    const float* __restrict__ e4, const float* __restrict__ e5,
    float* __restrict__ out)
{
    __shared__ float As[16][132];
    __shared__ float Bs[16][68];
    const int t  = threadIdx.x;
    const int m0 = blockIdx.x * 128;
    const int n0 = blockIdx.y * 64;
    const int tx = t & 15, ty = t >> 4;
    const int ar = t >> 2, kq = (t & 3) * 4;

    const int m_a0 = m0 + ar, m_a1 = m_a0 + 64;
    const int p0 = m_a0 % N_, hh0 = p0 / WW_, ww0 = p0 % WW_;
    const int p1 = m_a1 % N_, hh1 = p1 / WW_, ww1 = p1 % WW_;

    float acc[8][4];
#pragma unroll
    for (int i = 0; i < 8; i++)
#pragma unroll
        for (int j = 0; j < 4; j++) acc[i][j] = 0.f;

    for (int tap = 0; tap < 9; tap++) {
        const int dy = tap / 3 - 1, dx = tap % 3 - 1;
        const bool v0 = ((unsigned)(hh0 + dy) < (unsigned)HH_) && ((unsigned)(ww0 + dx) < (unsigned)WW_);
        const bool v1 = ((unsigned)(hh1 + dy) < (unsigned)HH_) && ((unsigned)(ww1 + dx) < (unsigned)WW_);
        const float* Ap0 = A + (size_t)(m_a0 + dy * WW_ + dx) * C_ + kq;
        const float* Ap1 = A + (size_t)(m_a1 + dy * WW_ + dx) * C_ + kq;
        const float* Bp  = Wt + (size_t)tap * C_ * C_ + (size_t)(n0 + ar) * C_ + kq;
        for (int kt = 0; kt < C_; kt += 16) {
            float4 a0 = v0 ? *(const float4*)(Ap0 + kt) : make_float4(0.f, 0.f, 0.f, 0.f);
            float4 a1 = v1 ? *(const float4*)(Ap1 + kt) : make_float4(0.f, 0.f, 0.f, 0.f);
            float4 bv = *(const float4*)(Bp + kt);
            __syncthreads();
            As[kq + 0][ar] = a0.x; As[kq + 1][ar] = a0.y; As[kq + 2][ar] = a0.z; As[kq + 3][ar] = a0.w;
            As[kq + 0][ar + 64] = a1.x; As[kq + 1][ar + 64] = a1.y;
            As[kq + 2][ar + 64] = a1.z; As[kq + 3][ar + 64] = a1.w;
            Bs[kq + 0][ar] = bv.x; Bs[kq + 1][ar] = bv.y; Bs[kq + 2][ar] = bv.z; Bs[kq + 3][ar] = bv.w;
            __syncthreads();
#pragma unroll
            for (int k = 0; k < 16; k++) {
                float4 x0 = *(const float4*)&As[k][ty * 8];
                float4 x1 = *(const float4*)&As[k][ty * 8 + 4];
                float4 y  = *(const float4*)&Bs[k][tx * 4];
                float am[8] = {x0.x, x0.y, x0.z, x0.w, x1.x, x1.y, x1.z, x1.w};
                float bm[4] = {y.x, y.y, y.z, y.w};
#pragma unroll
                for (int i = 0; i < 8; i++)
#pragma unroll
                    for (int j = 0; j < 4; j++) acc[i][j] = fmaf(am[i], bm[j], acc[i][j]);
            }
        }
    }
    do_epilogue<EPI>(acc, m0, n0, tx, ty, C_, e0, e1, e2, e3, e4, e5, out);
}

// ---------------- conv weight transpose: wt[tap][o][ci] = w[o][ci][tap] ----------------
__global__ void wtrans(const float* __restrict__ w, float* __restrict__ wt)
{
    int i = blockIdx.x * 256 + threadIdx.x;
    if (i >= 9 * C_ * C_) return;
    int tap = i / (C_ * C_);
    int rem = i - tap * (C_ * C_);
    int o = rem / C_, ci = rem - o * C_;
    wt[i] = w[(size_t)(o * C_ + ci) * 9 + tap];
}

// ---------------- reciprocal L2 norms of q,k rows (over N) ----------------
__global__ void rnorm_kernel()
{
    const int row = blockIdx.x;                 // s*6144 + b*384 + cc, s in {0,1}
    const float* base = g_qkvT + (size_t)row * N_;
    int t = threadIdx.x;
    float ss = 0.f;
    for (int i = t; i < N_; i += 256) { float v = base[i]; ss += v * v; }
    for (int o = 16; o; o >>= 1) ss += __shfl_down_sync(0xffffffffu, ss, o);
    __shared__ float sh[8];
    if ((t & 31) == 0) sh[t >> 5] = ss;
    __syncthreads();
    if (t == 0) {
        float S = sh[0] + sh[1] + sh[2] + sh[3] + sh[4] + sh[5] + sh[6] + sh[7];
        g_rn[row] = 1.0f / fmaxf(sqrtf(S), 1e-12f);
    }
}

// ---------------- S = (q_hat . k_hat) * temperature, one block per (b,h) ----------------
__global__ void attn_qk(const float* __restrict__ temp)
{
    const int bh = blockIdx.x;
    const int b = bh >> 3, h = bh & 7;
    __shared__ float qs[DD_ * 65];
    __shared__ float ks[DD_ * 65];
    const int t = threadIdx.x;
    const float* qbase = g_qkvT + ((size_t)(b)       * C_ + h * DD_) * N_;
    const float* kbase = g_qkvT + ((size_t)(B_ + b)  * C_ + h * DD_) * N_;
    float acc[3][3] = {};
    const int d0 = (t >> 4) * 3, e0i = (t & 15) * 3;
    for (int n0 = 0; n0 < N_; n0 += 64) {
        __syncthreads();
        for (int idx = t; idx < DD_ * 64; idx += 256) {
            int d = idx >> 6, nn = idx & 63;
            qs[d * 65 + nn] = qbase[(size_t)d * N_ + n0 + nn];
            ks[d * 65 + nn] = kbase[(size_t)d * N_ + n0 + nn];
        }
        __syncthreads();
#pragma unroll 4
        for (int nn = 0; nn < 64; nn++) {
            float q0 = qs[d0 * 65 + nn], q1 = qs[(d0 + 1) * 65 + nn], q2 = qs[(d0 + 2) * 65 + nn];
            float k0 = ks[e0i * 65 + nn], k1 = ks[(e0i + 1) * 65 + nn], k2 = ks[(e0i + 2) * 65 + nn];
            acc[0][0] += q0 * k0; acc[0][1] += q0 * k1; acc[0][2] += q0 * k2;
            acc[1][0] += q1 * k0; acc[1][1] += q1 * k1; acc[1][2] += q1 * k2;
            acc[2][0] += q2 * k0; acc[2][1] += q2 * k1; acc[2][2] += q2 * k2;
        }
    }
    const float tp = temp[h];
#pragma unroll
    for (int i = 0; i < 3; i++) {
        float rq = g_rn[b * C_ + h * DD_ + d0 + i];
#pragma unroll
        for (int j = 0; j < 3; j++) {
            float rk = g_rn[B_ * C_ + b * C_ + h * DD_ + e0i + j];
            g_attn[((size_t)bh * DD_ + d0 + i) * DD_ + e0i + j] = acc[i][j] * rq * rk * tp;
        }
    }
}

// ---------------- softmax over last axis (48), one thread per row ----------------
__global__ void softmax48()
{
    int row = blockIdx.x * blockDim.x + threadIdx.x;
    if (row >= B_ * NH_ * DD_) return;
    float* p = g_attn + (size_t)row * DD_;
    float mx = -1e30f;
#pragma unroll
    for (int i = 0; i < DD_; i++) mx = fmaxf(mx, p[i]);
    float s = 0.f;
#pragma unroll
    for (int i = 0; i < DD_; i++) { float e = expf(p[i] - mx); p[i] = e; s += e; }
    float r = 1.0f / s;
#pragma unroll
    for (int i = 0; i < DD_; i++) p[i] *= r;
}

// ---------------- out = P @ v, write transposed into [B,N,C] ----------------
__global__ void attn_v()
{
    const int nt = blockIdx.x;          // 0..17 (n tiles of 128)
    const int bh = blockIdx.y;
    const int b = bh >> 3, h = bh & 7;
    __shared__ float P[DD_ * DD_];
    __shared__ float vs[DD_ * 132];
    const int t = threadIdx.x;
    for (int idx = t; idx < DD_ * DD_; idx += 256) P[idx] = g_attn[(size_t)bh * DD_ * DD_ + idx];
    const float* vbase = g_qkvT + ((size_t)(2 * B_ + b) * C_ + h * DD_) * N_ + nt * 128;
    for (int idx = t; idx < DD_ * 128; idx += 256) {
        int e = idx >> 7, nn = idx & 127;
        vs[e * 132 + nn] = vbase[(size_t)e * N_ + nn];
    }
    __syncthreads();
    const int ng = t & 31, dg = t >> 5;
    const int n = ng * 4, dd0 = dg * 6;
    float acc[6][4] = {};
#pragma unroll 4
    for (int e = 0; e < DD_; e++) {
        float4 v4 = *(const float4*)&vs[e * 132 + n];
#pragma unroll
        for (int i = 0; i < 6; i++) {
            float pv = P[(dd0 + i) * DD_ + e];
            acc[i][0] += pv * v4.x; acc[i][1] += pv * v4.y;
            acc[i][2] += pv * v4.z; acc[i][3] += pv * v4.w;
        }
    }
    size_t mbase = ((size_t)b * N_ + nt * 128 + n) * C_ + h * DD_ + dd0;
#pragma unroll
    for (int i = 0; i < 6; i++)
#pragma unroll
        for (int jj = 0; jj < 4; jj++)
            g_onc[mbase + i + (size_t)jj * C_] = acc[i][jj];
}

// ---------------- tail: tuple scalars (H, W) if present ----------------
__global__ void tail_kernel(float* o, const int* pH, const int* pW, int extra)
{
    int i = threadIdx.x;
    if (i < extra) {
        float v = 0.f;
        if (i == 0) v = (float)(*pH);
        if (i == 1) v = (float)(*pW);
        o[(size_t)ROWS_ * C_ + i] = v;
    }
}

extern "C" void kernel_launch(void* const* d_in, const int* in_sizes, int n_in,
                              void* d_out, int out_size)
{
    const float* x      = (const float*)d_in[0];
    const float* ln1_g  = (const float*)d_in[1];
    const float* ln1_b  = (const float*)d_in[2];
    const float* w_qkv  = (const float*)d_in[3];
    const float* temp   = (const float*)d_in[4];
    const float* w_proj = (const float*)d_in[5];
    const float* gamma1 = (const float*)d_in[6];
    const float* ln2_g  = (const float*)d_in[7];
    const float* ln2_b  = (const float*)d_in[8];
    const float* mlp_w1 = (const float*)d_in[9];
    const float* bn1_g  = (const float*)d_in[10];
    const float* bn1_b  = (const float*)d_in[11];
    const float* bn1_m  = (const float*)d_in[12];
    const float* bn1_v  = (const float*)d_in[13];
    const float* mlp_w2 = (const float*)d_in[14];
    const float* bn2_g  = (const float*)d_in[15];
    const float* bn2_b  = (const float*)d_in[16];
    const float* bn2_m  = (const float*)d_in[17];
    const float* bn2_v  = (const float*)d_in[18];
    const float* gamma2 = (const float*)d_in[19];
    const float* ln3_g  = (const float*)d_in[20];
    const float* ln3_b  = (const float*)d_in[21];
    const float* pconv1 = (const float*)d_in[22];
    const float* pbn_g  = (const float*)d_in[23];
    const float* pbn_b  = (const float*)d_in[24];
    const float* pbn_m  = (const float*)d_in[25];
    const float* pbn_v  = (const float*)d_in[26];
    const float* pconv2 = (const float*)d_in[27];
    const float* gamma3 = (const float*)d_in[28];
    const int*   pH     = (const int*)d_in[29];
    const int*   pW     = (const int*)d_in[30];
    float* dout = (float*)d_out;

    float *xn, *qkvT, *onc, *x1, *hid, *x2, *c1, *wt1, *wt2;
    cudaGetSymbolAddress((void**)&xn,   g_xn);
    cudaGetSymbolAddress((void**)&qkvT, g_qkvT);
    cudaGetSymbolAddress((void**)&onc,  g_onc);
    cudaGetSymbolAddress((void**)&x1,   g_x1);
    cudaGetSymbolAddress((void**)&hid,  g_hid);
    cudaGetSymbolAddress((void**)&x2,   g_x2);
    cudaGetSymbolAddress((void**)&c1,   g_c1);
    cudaGetSymbolAddress((void**)&wt1,  g_wt1);
    cudaGetSymbolAddress((void**)&wt2,  g_wt2);

    const float* np = nullptr;
    const int WTN = (9 * C_ * C_ + 255) / 256;

    // conv weight re-layout
    wtrans<<<WTN, 256>>>(pconv1, wt1);
    wtrans<<<WTN, 256>>>(pconv2, wt2);

    // --- attention block ---
    ln_kernel<<<ROWS_, 128>>>(x, ln1_g, ln1_b, xn);
    gemm_nt<0><<<dim3(288, 18), 256>>>(xn, w_qkv, C_, 0, np, np, np, np, np, np, qkvT);
    rnorm_kernel<<<2 * B_ * C_, 256>>>();
    attn_qk<<<B_ * NH_, 256>>>(temp);
    softmax48<<<(B_ * NH_ * DD_ + 255) / 256, 256>>>();
    attn_v<<<dim3(18, B_ * NH_), 256>>>();
    gemm_nt<1><<<dim3(288, 6), 256>>>(onc, w_proj, C_, C_, np, np, np, np, x, gamma1, x1);

    // --- ConvMlp block (1x1 convs + BN) ---
    ln_kernel<<<ROWS_, 128>>>(x1, ln2_g, ln2_b, xn);
    gemm_nt<2><<<dim3(288, 12), 256>>>(xn, mlp_w1, C_, C2_, bn1_g, bn1_b, bn1_m, bn1_v, np, np, hid);
    gemm_nt<3><<<dim3(288, 6), 256>>>(hid, mlp_w2, C2_, C_, bn2_g, bn2_b, bn2_m, bn2_v, x1, gamma2, x2);

    // --- projection block (3x3 convs) ---
    ln_kernel<<<ROWS_, 128>>>(x2, ln3_g, ln3_b, xn);
    conv_gemm<2><<<dim3(288, 6), 256>>>(xn, wt1, pbn_g, pbn_b, pbn_m, pbn_v, np, np, c1);
    conv_gemm<1><<<dim3(288, 6), 256>>>(c1, wt2, np, np, np, np, x2, gamma3, dout);

    int extra = out_size - (int)((size_t)ROWS_ * C_);
    if (extra > 0) tail_kernel<<<1, 32>>>(dout, pH, pW, extra);
}

// round 5
// speedup vs baseline: 3.9080x; 3.9080x over previous
#include <cuda_runtime.h>
#include <cuda_bf16.h>
#include <math.h>
#include <stdint.h>

#define B_    16
#define HH_   48
#define WW_   48
#define N_    2304
#define C_    384
#define C2_   768
#define NH_   8
#define DD_   48
#define ROWS_ 36864

typedef __nv_bfloat16 bf16;

// ---------------- device scratch ----------------
__device__ bf16  g_xnb [(size_t)ROWS_ * C_];
__device__ float g_qkvT[(size_t)3 * B_ * C_ * N_];   // [s][b][cc][n] fp32
__device__ float g_rn  [2 * B_ * C_];
__device__ float g_attn[B_ * NH_ * DD_ * DD_];
__device__ bf16  g_oncb[(size_t)ROWS_ * C_];
__device__ float g_x1  [(size_t)ROWS_ * C_];
__device__ bf16  g_hidb[(size_t)ROWS_ * C2_];
__device__ float g_x2  [(size_t)ROWS_ * C_];
__device__ bf16  g_c1b [(size_t)ROWS_ * C_];
__device__ bf16  g_wqkvb[3 * C_ * C_];
__device__ bf16  g_wprojb[C_ * C_];
__device__ bf16  g_w1b [C2_ * C_];
__device__ bf16  g_w2b [C_ * C2_];
__device__ bf16  g_wt1b[9 * C_ * C_];
__device__ bf16  g_wt2b[9 * C_ * C_];

__device__ __forceinline__ float gelu_f(float v) {
    return 0.5f * v * (1.0f + erff(v * 0.70710678118654752440f));
}

__device__ __forceinline__ uint32_t smem_u32(const void* p) {
    uint32_t r;
    asm("{ .reg .u64 t; cvta.to.shared.u64 t, %1; cvt.u32.u64 %0, t; }" : "=r"(r) : "l"(p));
    return r;
}
#define SW128(o) ((o) ^ (((o) >> 3) & 0x70))

__device__ __forceinline__ void ldm4(uint32_t (&d)[4], uint32_t addr) {
    asm volatile("ldmatrix.sync.aligned.m8n8.x4.shared.b16 {%0,%1,%2,%3}, [%4];"
                 : "=r"(d[0]), "=r"(d[1]), "=r"(d[2]), "=r"(d[3]) : "r"(addr));
}
__device__ __forceinline__ void mma16816(float (&c)[4], const uint32_t (&a)[4],
                                         uint32_t b0, uint32_t b1) {
    asm volatile("mma.sync.aligned.m16n8k16.row.col.f32.bf16.bf16.f32 "
                 "{%0,%1,%2,%3}, {%4,%5,%6,%7}, {%8,%9}, {%0,%1,%2,%3};"
                 : "+f"(c[0]), "+f"(c[1]), "+f"(c[2]), "+f"(c[3])
                 : "r"(a[0]), "r"(a[1]), "r"(a[2]), "r"(a[3]), "r"(b0), "r"(b1));
}

// smem: A0 16K | B0 8K | A1 16K | B1 8K  (48KB)
#define SA0 0
#define SB0 16384
#define SA1 24576
#define SB1 40960
#define SMEM_BYTES 49152

// ---------------- MMA compute for one K=64 stage ----------------
__device__ __forceinline__ void stage_mma(uint32_t sbase, uint32_t Aoff, uint32_t Boff,
                                          int am_base, int bn_base, int lane,
                                          float (&acc)[2][4][4])
{
    const int arow = ((lane >> 3) & 1) * 8 + (lane & 7);
    const int akb  = ((lane >> 4) & 1) * 16;          // A k-block byte offset
    const int brow = ((lane >> 4) & 1) * 8 + (lane & 7);
    const int bkb  = ((lane >> 3) & 1) * 16;
#pragma unroll
    for (int kk = 0; kk < 64; kk += 16) {
        uint32_t a0[4], a1[4], b0[4], b1[4];
        ldm4(a0, sbase + Aoff + SW128((am_base + arow) * 128 + kk * 2 + akb));
        ldm4(a1, sbase + Aoff + SW128((am_base + 16 + arow) * 128 + kk * 2 + akb));
        ldm4(b0, sbase + Boff + SW128((bn_base + brow) * 128 + kk * 2 + bkb));
        ldm4(b1, sbase + Boff + SW128((bn_base + 16 + brow) * 128 + kk * 2 + bkb));
        mma16816(acc[0][0], a0, b0[0], b0[1]);
        mma16816(acc[0][1], a0, b0[2], b0[3]);
        mma16816(acc[0][2], a0, b1[0], b1[1]);
        mma16816(acc[0][3], a0, b1[2], b1[3]);
        mma16816(acc[1][0], a1, b0[0], b0[1]);
        mma16816(acc[1][1], a1, b0[2], b0[3]);
        mma16816(acc[1][2], a1, b1[0], b1[1]);
        mma16816(acc[1][3], a1, b1[2], b1[3]);
    }
}

__device__ __forceinline__ void store_stage(char* smem, uint32_t Aoff, uint32_t Boff,
                                            int r0, int q, const uint4 (&pa)[4], const uint4 (&pb)[2])
{
#pragma unroll
    for (int it = 0; it < 4; it++)
        *(uint4*)(smem + Aoff + SW128((r0 + it * 32) * 128 + q * 16)) = pa[it];
#pragma unroll
    for (int it = 0; it < 2; it++)
        *(uint4*)(smem + Boff + SW128((r0 + it * 32) * 128 + q * 16)) = pb[it];
}

// ---------------- epilogues ----------------
// EPI 0: qkv transposed scatter (via smem). 1: out=e4+e5*acc. 2: gelu(bn) -> bf16. 3: e4+e5*bn.
template <int EPI, typename OutT>
__device__ __forceinline__ void epi_frag(float (&acc)[2][4][4], char* smem,
                                         int m0, int n0, int wm, int wn, int lane, int t, int ldo,
                                         const float* __restrict__ e0, const float* __restrict__ e1,
                                         const float* __restrict__ e2, const float* __restrict__ e3,
                                         const float* __restrict__ e4, const float* __restrict__ e5,
                                         OutT* __restrict__ out)
{
    const int rIn = lane >> 2, cpair = (lane & 3) * 2;
    if (EPI == 0) {
        // stage transposed tile [64 n][132 pad][m 128] in smem (fp32)
        float* smf = (float*)smem;
        __syncthreads();
#pragma unroll
        for (int ni = 0; ni < 4; ni++) {
            const int cl = wn * 32 + ni * 8 + cpair;
#pragma unroll
            for (int mi = 0; mi < 2; mi++) {
#pragma unroll
                for (int h = 0; h < 2; h++) {
                    const int rl = wm * 32 + mi * 16 + rIn + h * 8;
                    smf[(cl + 0) * 132 + rl] = acc[mi][ni][2 * h + 0];
                    smf[(cl + 1) * 132 + rl] = acc[mi][ni][2 * h + 1];
                }
            }
        }
        __syncthreads();
        const int b = m0 / N_;
        const int nrow0 = (m0 - b * N_);
        const int rown = t & 63, seg = t >> 6;
        const int rr = n0 + rown;
        const int s = rr / C_, cc = rr - s * C_;
        float* dst = (float*)out + ((size_t)(s * B_ + b) * C_ + cc) * (size_t)N_ + nrow0 + seg * 32;
        const float* src = smf + rown * 132 + seg * 32;
#pragma unroll
        for (int i = 0; i < 8; i++)
            *(float4*)(dst + i * 4) = *(const float4*)(src + i * 4);
        return;
    }
#pragma unroll
    for (int ni = 0; ni < 4; ni++) {
        const int col = n0 + wn * 32 + ni * 8 + cpair;
        float s0 = 1.f, s1 = 1.f, bi0 = 0.f, bi1 = 0.f, g0 = 0.f, g1 = 0.f;
        if (EPI == 2 || EPI == 3) {
            s0 = e0[col + 0] * rsqrtf(e3[col + 0] + 1e-5f);
            s1 = e0[col + 1] * rsqrtf(e3[col + 1] + 1e-5f);
            bi0 = e1[col + 0] - e2[col + 0] * s0;
            bi1 = e1[col + 1] - e2[col + 1] * s1;
        }
        if (EPI == 1 || EPI == 3) { g0 = e5[col]; g1 = e5[col + 1]; }
#pragma unroll
        for (int mi = 0; mi < 2; mi++) {
#pragma unroll
            for (int h = 0; h < 2; h++) {
                const int row = m0 + wm * 32 + mi * 16 + rIn + h * 8;
                float a0 = acc[mi][ni][2 * h + 0];
                float a1 = acc[mi][ni][2 * h + 1];
                if (EPI == 2 || EPI == 3) { a0 = a0 * s0 + bi0; a1 = a1 * s1 + bi1; }
                if (EPI == 2) { a0 = gelu_f(a0); a1 = gelu_f(a1); }
                const size_t off = (size_t)row * ldo + col;
                if (EPI == 1 || EPI == 3) {
                    float2 xr = *(const float2*)(e4 + off);
                    a0 = xr.x + g0 * a0; a1 = xr.y + g1 * a1;
                }
                if (sizeof(OutT) == 2) {
                    __nv_bfloat162 p = __floats2bfloat162_rn(a0, a1);
                    *(uint32_t*)((bf16*)out + off) = *(uint32_t*)&p;
                } else {
                    *(float2*)((float*)out + off) = make_float2(a0, a1);
                }
            }
        }
    }
}

// ---------------- dense NT GEMM: D[128x64] = A[128xK] * Bw[64xK]^T ----------------
template <int EPI, typename OutT>
__global__ void __launch_bounds__(256, 2) tc_gemm(
    const bf16* __restrict__ A, const bf16* __restrict__ Bw, int K, int ldo,
    const float* __restrict__ e0, const float* __restrict__ e1,
    const float* __restrict__ e2, const float* __restrict__ e3,
    const float* __restrict__ e4, const float* __restrict__ e5,
    OutT* __restrict__ out)
{
    extern __shared__ char smem[];
    const int t = threadIdx.x, wid = t >> 5, lane = t & 31;
    const int m0 = blockIdx.x * 128, n0 = blockIdx.y * 64;
    const int wm = wid & 3, wn = wid >> 2;
    const uint32_t sbase = smem_u32(smem);
    const int q = t & 7, r0 = t >> 3;
    const int nc = K >> 6;

    float acc[2][4][4];
#pragma unroll
    for (int i = 0; i < 2; i++)
#pragma unroll
        for (int j = 0; j < 4; j++)
#pragma unroll
            for (int k = 0; k < 4; k++) acc[i][j][k] = 0.f;

    const char* Abase = (const char*)(A + (size_t)m0 * K);
    const char* Bbase = (const char*)(Bw + (size_t)n0 * K);
    const size_t rsA = (size_t)K * 2;

    uint4 pa[4], pb[2];
    // stage 0
#pragma unroll
    for (int it = 0; it < 4; it++)
        pa[it] = *(const uint4*)(Abase + (size_t)(r0 + it * 32) * rsA + q * 16);
#pragma unroll
    for (int it = 0; it < 2; it++)
        pb[it] = *(const uint4*)(Bbase + (size_t)(r0 + it * 32) * rsA + q * 16);
    store_stage(smem, SA0, SB0, r0, q, pa, pb);
    __syncthreads();

    for (int c = 0; c < nc; c++) {
        const int buf = c & 1;
        if (c + 1 < nc) {
            const size_t ko = (size_t)(c + 1) * 128;   // 64 bf16 = 128 bytes
#pragma unroll
            for (int it = 0; it < 4; it++)
                pa[it] = *(const uint4*)(Abase + (size_t)(r0 + it * 32) * rsA + ko + q * 16);
#pragma unroll
            for (int it = 0; it < 2; it++)
                pb[it] = *(const uint4*)(Bbase + (size_t)(r0 + it * 32) * rsA + ko + q * 16);
        }
        stage_mma(sbase, buf ? SA1 : SA0, buf ? SB1 : SB0, wm * 32, wn * 32, lane, acc);
        __syncthreads();
        if (c + 1 < nc) {
            store_stage(smem, buf ? SA0 : SA1, buf ? SB0 : SB1, r0, q, pa, pb);
            __syncthreads();
        }
    }
    epi_frag<EPI, OutT>(acc, smem, m0, n0, wm, wn, lane, t, ldo, e0, e1, e2, e3, e4, e5, out);
}

// ---------------- 3x3 conv as 9-tap K-accumulated GEMM ----------------
template <int EPI, typename OutT>
__global__ void __launch_bounds__(256, 2) tc_conv(
    const bf16* __restrict__ A, const bf16* __restrict__ Wt,
    const float* __restrict__ e0, const float* __restrict__ e1,
    const float* __restrict__ e2, const float* __restrict__ e3,
    const float* __restrict__ e4, const float* __restrict__ e5,
    OutT* __restrict__ out)
{
    extern __shared__ char smem[];
    const int t = threadIdx.x, wid = t >> 5, lane = t & 31;
    const int m0 = blockIdx.x * 128, n0 = blockIdx.y * 64;
    const int wm = wid & 3, wn = wid >> 2;
    const uint32_t sbase = smem_u32(smem);
    const int q = t & 7, r0 = t >> 3;

    const int m0p = m0 % N_;
    int hh[4], ww[4];
#pragma unroll
    for (int it = 0; it < 4; it++) {
        int p = m0p + r0 + it * 32;
        hh[it] = p / WW_;
        ww[it] = p - hh[it] * WW_;
    }

    float acc[2][4][4];
#pragma unroll
    for (int i = 0; i < 2; i++)
#pragma unroll
        for (int j = 0; j < 4; j++)
#pragma unroll
            for (int k = 0; k < 4; k++) acc[i][j][k] = 0.f;

    uint4 pa[4], pb[2];

    auto fetch = [&](int c, uint4 (&fa)[4], uint4 (&fb)[2]) {
        const int tap = c / 6, kc = c - tap * 6;
        const int dy = tap / 3 - 1, dx = tap % 3 - 1;
        const bf16* Atap = A + (size_t)(m0 + dy * WW_ + dx) * C_ + kc * 64;
        const bf16* Wtap = Wt + (size_t)tap * C_ * C_ + (size_t)n0 * C_ + kc * 64;
#pragma unroll
        for (int it = 0; it < 4; it++) {
            bool ok = ((unsigned)(hh[it] + dy) < (unsigned)HH_) &&
                      ((unsigned)(ww[it] + dx) < (unsigned)WW_);
            uint4 v = make_uint4(0, 0, 0, 0);
            if (ok)
                v = *(const uint4*)((const char*)(Atap + (size_t)(r0 + it * 32) * C_) + q * 16);
            fa[it] = v;
        }
#pragma unroll
        for (int it = 0; it < 2; it++)
            fb[it] = *(const uint4*)((const char*)(Wtap + (size_t)(r0 + it * 32) * C_) + q * 16);
    };

    fetch(0, pa, pb);
    store_stage(smem, SA0, SB0, r0, q, pa, pb);
    __syncthreads();

    const int nc = 54;
    for (int c = 0; c < nc; c++) {
        const int buf = c & 1;
        if (c + 1 < nc) fetch(c + 1, pa, pb);
        stage_mma(sbase, buf ? SA1 : SA0, buf ? SB1 : SB0, wm * 32, wn * 32, lane, acc);
        __syncthreads();
        if (c + 1 < nc) {
            store_stage(smem, buf ? SA0 : SA1, buf ? SB0 : SB1, r0, q, pa, pb);
            __syncthreads();
        }
    }
    epi_frag<EPI, OutT>(acc, smem, m0, n0, wm, wn, lane, t, C_, e0, e1, e2, e3, e4, e5, out);
}

// ---------------- LayerNorm -> bf16 ----------------
__global__ void ln_kernel(const float* __restrict__ in, const float* __restrict__ g,
                          const float* __restrict__ b, bf16* __restrict__ outp)
{
    const int r = blockIdx.x;
    const int t = threadIdx.x;
    const float* row = in + (size_t)r * C_;
    float v0 = row[t], v1 = row[t + 128], v2 = row[t + 256];
    float s = v0 + v1 + v2;
    float ss = v0 * v0 + v1 * v1 + v2 * v2;
    for (int o = 16; o; o >>= 1) {
        s  += __shfl_down_sync(0xffffffffu, s,  o);
        ss += __shfl_down_sync(0xffffffffu, ss, o);
    }
    __shared__ float sh[8];
    if ((t & 31) == 0) { sh[t >> 5] = s; sh[4 + (t >> 5)] = ss; }
    __syncthreads();
    if (t == 0) {
        float S  = sh[0] + sh[1] + sh[2] + sh[3];
        float SS = sh[4] + sh[5] + sh[6] + sh[7];
        float mean = S * (1.0f / C_);
        float var  = SS * (1.0f / C_) - mean * mean;
        sh[0] = mean;
        sh[1] = rsqrtf(var + 1e-5f);
    }
    __syncthreads();
    float mean = sh[0], rstd = sh[1];
    bf16* orow = outp + (size_t)r * C_;
    orow[t]       = __float2bfloat16_rn((v0 - mean) * rstd * g[t]       + b[t]);
    orow[t + 128] = __float2bfloat16_rn((v1 - mean) * rstd * g[t + 128] + b[t + 128]);
    orow[t + 256] = __float2bfloat16_rn((v2 - mean) * rstd * g[t + 256] + b[t + 256]);
}

// ---------------- conversions ----------------
__global__ void f2bf(const float* __restrict__ in, bf16* __restrict__ outp, int n)
{
    int i = blockIdx.x * 256 + threadIdx.x;
    if (i < n) outp[i] = __float2bfloat16_rn(in[i]);
}
__global__ void wtrans_bf(const float* __restrict__ w, bf16* __restrict__ wt)
{
    int i = blockIdx.x * 256 + threadIdx.x;
    if (i >= 9 * C_ * C_) return;
    int tap = i / (C_ * C_);
    int rem = i - tap * (C_ * C_);
    int o = rem / C_, ci = rem - o * C_;
    wt[i] = __float2bfloat16_rn(w[(size_t)(o * C_ + ci) * 9 + tap]);
}

// ---------------- attention small kernels (fp32 qkvT) ----------------
__global__ void rnorm_kernel()
{
    const int row = blockIdx.x;
    const float* base = g_qkvT + (size_t)row * N_;
    int t = threadIdx.x;
    float ss = 0.f;
    for (int i = t; i < N_; i += 256) { float v = base[i]; ss += v * v; }
    for (int o = 16; o; o >>= 1) ss += __shfl_down_sync(0xffffffffu, ss, o);
    __shared__ float sh[8];
    if ((t & 31) == 0) sh[t >> 5] = ss;
    __syncthreads();
    if (t == 0) {
        float S = sh[0] + sh[1] + sh[2] + sh[3] + sh[4] + sh[5] + sh[6] + sh[7];
        g_rn[row] = 1.0f / fmaxf(sqrtf(S), 1e-12f);
    }
}

__global__ void attn_qk(const float* __restrict__ temp)
{
    const int bh = blockIdx.x;
    const int b = bh >> 3, h = bh & 7;
    __shared__ float qs[DD_ * 65];
    __shared__ float ks[DD_ * 65];
    const int t = threadIdx.x;
    const float* qbase = g_qkvT + ((size_t)(b)      * C_ + h * DD_) * N_;
    const float* kbase = g_qkvT + ((size_t)(B_ + b) * C_ + h * DD_) * N_;
    float acc[3][3] = {};
    const int d0 = (t >> 4) * 3, e0i = (t & 15) * 3;
    for (int n0 = 0; n0 < N_; n0 += 64) {
        __syncthreads();
        for (int idx = t; idx < DD_ * 64; idx += 256) {
            int d = idx >> 6, nn = idx & 63;
            qs[d * 65 + nn] = qbase[(size_t)d * N_ + n0 + nn];
            ks[d * 65 + nn] = kbase[(size_t)d * N_ + n0 + nn];
        }
        __syncthreads();
#pragma unroll 4
        for (int nn = 0; nn < 64; nn++) {
            float q0 = qs[d0 * 65 + nn], q1 = qs[(d0 + 1) * 65 + nn], q2 = qs[(d0 + 2) * 65 + nn];
            float k0 = ks[e0i * 65 + nn], k1 = ks[(e0i + 1) * 65 + nn], k2 = ks[(e0i + 2) * 65 + nn];
            acc[0][0] += q0 * k0; acc[0][1] += q0 * k1; acc[0][2] += q0 * k2;
            acc[1][0] += q1 * k0; acc[1][1] += q1 * k1; acc[1][2] += q1 * k2;
            acc[2][0] += q2 * k0; acc[2][1] += q2 * k1; acc[2][2] += q2 * k2;
        }
    }
    const float tp = temp[h];
#pragma unroll
    for (int i = 0; i < 3; i++) {
        float rq = g_rn[b * C_ + h * DD_ + d0 + i];
#pragma unroll
        for (int j = 0; j < 3; j++) {
            float rk = g_rn[B_ * C_ + b * C_ + h * DD_ + e0i + j];
            g_attn[((size_t)bh * DD_ + d0 + i) * DD_ + e0i + j] = acc[i][j] * rq * rk * tp;
        }
    }
}

__global__ void softmax48()
{
    int row = blockIdx.x * blockDim.x + threadIdx.x;
    if (row >= B_ * NH_ * DD_) return;
    float* p = g_attn + (size_t)row * DD_;
    float mx = -1e30f;
#pragma unroll
    for (int i = 0; i < DD_; i++) mx = fmaxf(mx, p[i]);
    float s = 0.f;
#pragma unroll
    for (int i = 0; i < DD_; i++) { float e = expf(p[i] - mx); p[i] = e; s += e; }
    float r = 1.0f / s;
#pragma unroll
    for (int i = 0; i < DD_; i++) p[i] *= r;
}

__global__ void attn_v()
{
    const int nt = blockIdx.x;
    const int bh = blockIdx.y;
    const int b = bh >> 3, h = bh & 7;
    __shared__ float P[DD_ * DD_];
    __shared__ float vs[DD_ * 132];
    const int t = threadIdx.x;
    for (int idx = t; idx < DD_ * DD_; idx += 256) P[idx] = g_attn[(size_t)bh * DD_ * DD_ + idx];
    const float* vbase = g_qkvT + ((size_t)(2 * B_ + b) * C_ + h * DD_) * N_ + nt * 128;
    for (int idx = t; idx < DD_ * 128; idx += 256) {
        int e = idx >> 7, nn = idx & 127;
        vs[e * 132 + nn] = vbase[(size_t)e * N_ + nn];
    }
    __syncthreads();
    const int ng = t & 31, dg = t >> 5;
    const int n = ng * 4, dd0 = dg * 6;
    float acc[6][4] = {};
#pragma unroll 4
    for (int e = 0; e < DD_; e++) {
        float4 v4 = *(const float4*)&vs[e * 132 + n];
#pragma unroll
        for (int i = 0; i < 6; i++) {
            float pv = P[(dd0 + i) * DD_ + e];
            acc[i][0] += pv * v4.x; acc[i][1] += pv * v4.y;
            acc[i][2] += pv * v4.z; acc[i][3] += pv * v4.w;
        }
    }
    size_t mbase = ((size_t)b * N_ + nt * 128 + n) * C_ + h * DD_ + dd0;
#pragma unroll
    for (int i = 0; i < 6; i++)
#pragma unroll
        for (int jj = 0; jj < 4; jj++)
            g_oncb[mbase + i + (size_t)jj * C_] = __float2bfloat16_rn(acc[i][jj]);
}

__global__ void tail_kernel(float* o, const int* pH, const int* pW, int extra)
{
    int i = threadIdx.x;
    if (i < extra) {
        float v = 0.f;
        if (i == 0) v = (float)(*pH);
        if (i == 1) v = (float)(*pW);
        o[(size_t)ROWS_ * C_ + i] = v;
    }
}

extern "C" void kernel_launch(void* const* d_in, const int* in_sizes, int n_in,
                              void* d_out, int out_size)
{
    const float* x      = (const float*)d_in[0];
    const float* ln1_g  = (const float*)d_in[1];
    const float* ln1_b  = (const float*)d_in[2];
    const float* w_qkv  = (const float*)d_in[3];
    const float* temp   = (const float*)d_in[4];
    const float* w_proj = (const float*)d_in[5];
    const float* gamma1 = (const float*)d_in[6];
    const float* ln2_g  = (const float*)d_in[7];
    const float* ln2_b  = (const float*)d_in[8];
    const float* mlp_w1 = (const float*)d_in[9];
    const float* bn1_g  = (const float*)d_in[10];
    const float* bn1_b  = (const float*)d_in[11];
    const float* bn1_m  = (const float*)d_in[12];
    const float* bn1_v  = (const float*)d_in[13];
    const float* mlp_w2 = (const float*)d_in[14];
    const float* bn2_g  = (const float*)d_in[15];
    const float* bn2_b  = (const float*)d_in[16];
    const float* bn2_m  = (const float*)d_in[17];
    const float* bn2_v  = (const float*)d_in[18];
    const float* gamma2 = (const float*)d_in[19];
    const float* ln3_g  = (const float*)d_in[20];
    const float* ln3_b  = (const float*)d_in[21];
    const float* pconv1 = (const float*)d_in[22];
    const float* pbn_g  = (const float*)d_in[23];
    const float* pbn_b  = (const float*)d_in[24];
    const float* pbn_m  = (const float*)d_in[25];
    const float* pbn_v  = (const float*)d_in[26];
    const float* pconv2 = (const float*)d_in[27];
    const float* gamma3 = (const float*)d_in[28];
    const int*   pH     = (const int*)d_in[29];
    const int*   pW     = (const int*)d_in[30];
    float* dout = (float*)d_out;

    bf16 *xnb, *oncb, *hidb, *c1b, *wqkvb, *wprojb, *w1b, *w2b, *wt1b, *wt2b;
    float *qkvT, *x1, *x2;
    cudaGetSymbolAddress((void**)&xnb,    g_xnb);
    cudaGetSymbolAddress((void**)&qkvT,   g_qkvT);
    cudaGetSymbolAddress((void**)&oncb,   g_oncb);
    cudaGetSymbolAddress((void**)&x1,     g_x1);
    cudaGetSymbolAddress((void**)&hidb,   g_hidb);
    cudaGetSymbolAddress((void**)&x2,     g_x2);
    cudaGetSymbolAddress((void**)&c1b,    g_c1b);
    cudaGetSymbolAddress((void**)&wqkvb,  g_wqkvb);
    cudaGetSymbolAddress((void**)&wprojb, g_wprojb);
    cudaGetSymbolAddress((void**)&w1b,    g_w1b);
    cudaGetSymbolAddress((void**)&w2b,    g_w2b);
    cudaGetSymbolAddress((void**)&wt1b,   g_wt1b);
    cudaGetSymbolAddress((void**)&wt2b,   g_wt2b);

    const float* np = nullptr;

    // weight conversions
    f2bf<<<(3 * C_ * C_ + 255) / 256, 256>>>(w_qkv, wqkvb, 3 * C_ * C_);
    f2bf<<<(C_ * C_ + 255) / 256, 256>>>(w_proj, wprojb, C_ * C_);
    f2bf<<<(C2_ * C_ + 255) / 256, 256>>>(mlp_w1, w1b, C2_ * C_);
    f2bf<<<(C_ * C2_ + 255) / 256, 256>>>(mlp_w2, w2b, C_ * C2_);
    wtrans_bf<<<(9 * C_ * C_ + 255) / 256, 256>>>(pconv1, wt1b);
    wtrans_bf<<<(9 * C_ * C_ + 255) / 256, 256>>>(pconv2, wt2b);

    // --- attention block ---
    ln_kernel<<<ROWS_, 128>>>(x, ln1_g, ln1_b, xnb);
    tc_gemm<0, float><<<dim3(288, 18), 256, SMEM_BYTES>>>(xnb, wqkvb, C_, 0, np, np, np, np, np, np, qkvT);
    rnorm_kernel<<<2 * B_ * C_, 256>>>();
    attn_qk<<<B_ * NH_, 256>>>(temp);
    softmax48<<<(B_ * NH_ * DD_ + 255) / 256, 256>>>();
    attn_v<<<dim3(18, B_ * NH_), 256>>>();
    tc_gemm<1, float><<<dim3(288, 6), 256, SMEM_BYTES>>>(oncb, wprojb, C_, C_, np, np, np, np, x, gamma1, x1);

    // --- ConvMlp block ---
    ln_kernel<<<ROWS_, 128>>>(x1, ln2_g, ln2_b, xnb);
    tc_gemm<2, bf16><<<dim3(288, 12), 256, SMEM_BYTES>>>(xnb, w1b, C_, C2_, bn1_g, bn1_b, bn1_m, bn1_v, np, np, hidb);
    tc_gemm<3, float><<<dim3(288, 6), 256, SMEM_BYTES>>>(hidb, w2b, C2_, C_, bn2_g, bn2_b, bn2_m, bn2_v, x1, gamma2, x2);

    // --- projection block (3x3 convs) ---
    ln_kernel<<<ROWS_, 128>>>(x2, ln3_g, ln3_b, xnb);
    tc_conv<2, bf16><<<dim3(288, 6), 256, SMEM_BYTES>>>(xnb, wt1b, pbn_g, pbn_b, pbn_m, pbn_v, np, np, c1b);
    tc_conv<1, float><<<dim3(288, 6), 256, SMEM_BYTES>>>(c1b, wt2b, np, np, np, np, x2, gamma3, dout);

    int extra = out_size - (int)((size_t)ROWS_ * C_);
    if (extra > 0) tail_kernel<<<1, 32>>>(dout, pH, pW, extra);
}

// round 6
// speedup vs baseline: 4.7220x; 1.2083x over previous
#include <cuda_runtime.h>
#include <cuda_bf16.h>
#include <math.h>
#include <stdint.h>

#define B_    16
#define HH_   48
#define WW_   48
#define N_    2304
#define C_    384
#define C2_   768
#define NH_   8
#define DD_   48
#define ROWS_ 36864

typedef __nv_bfloat16 bf16;

// ---------------- device scratch ----------------
__device__ bf16  g_xnb [(size_t)ROWS_ * C_];
__device__ bf16  g_qkvT[(size_t)3 * B_ * C_ * N_];   // [s][b][cc][n] bf16
__device__ float g_rn  [2 * B_ * C_];
__device__ float g_attn[B_ * NH_ * DD_ * DD_];
__device__ bf16  g_oncb[(size_t)ROWS_ * C_];
__device__ float g_x1  [(size_t)ROWS_ * C_];
__device__ bf16  g_hidb[(size_t)ROWS_ * C2_];
__device__ float g_x2  [(size_t)ROWS_ * C_];
__device__ bf16  g_c1b [(size_t)ROWS_ * C_];
__device__ bf16  g_wqkvb[3 * C_ * C_];
__device__ bf16  g_wprojb[C_ * C_];
__device__ bf16  g_w1b [C2_ * C_];
__device__ bf16  g_w2b [C_ * C2_];
__device__ bf16  g_wt1b[9 * C_ * C_];
__device__ bf16  g_wt2b[9 * C_ * C_];

__device__ __forceinline__ float gelu_f(float v) {
    return 0.5f * v * (1.0f + erff(v * 0.70710678118654752440f));
}

__device__ __forceinline__ uint32_t smem_u32(const void* p) {
    uint32_t r;
    asm("{ .reg .u64 t; cvta.to.shared.u64 t, %1; cvt.u32.u64 %0, t; }" : "=r"(r) : "l"(p));
    return r;
}
#define SW128(o) ((o) ^ (((o) >> 3) & 0x70))

__device__ __forceinline__ void ldm4(uint32_t (&d)[4], uint32_t addr) {
    asm volatile("ldmatrix.sync.aligned.m8n8.x4.shared.b16 {%0,%1,%2,%3}, [%4];"
                 : "=r"(d[0]), "=r"(d[1]), "=r"(d[2]), "=r"(d[3]) : "r"(addr));
}
__device__ __forceinline__ void mma16816(float (&c)[4], const uint32_t (&a)[4],
                                         uint32_t b0, uint32_t b1) {
    asm volatile("mma.sync.aligned.m16n8k16.row.col.f32.bf16.bf16.f32 "
                 "{%0,%1,%2,%3}, {%4,%5,%6,%7}, {%8,%9}, {%0,%1,%2,%3};"
                 : "+f"(c[0]), "+f"(c[1]), "+f"(c[2]), "+f"(c[3])
                 : "r"(a[0]), "r"(a[1]), "r"(a[2]), "r"(a[3]), "r"(b0), "r"(b1));
}
__device__ __forceinline__ void cpa16(uint32_t dst, const void* src) {
    asm volatile("cp.async.cg.shared.global [%0], [%1], 16;" :: "r"(dst), "l"(src));
}
__device__ __forceinline__ void cpa16z(uint32_t dst, const void* src, bool ok) {
    int sz = ok ? 16 : 0;
    asm volatile("cp.async.cg.shared.global [%0], [%1], 16, %2;" :: "r"(dst), "l"(src), "r"(sz));
}
#define CP_COMMIT() asm volatile("cp.async.commit_group;" ::: "memory")

// smem: 3 stages x (A 16K + B 8K) = 72KB
#define STAGES 3
#define STAGE_BYTES 24576
#define SMEM_BYTES (STAGES * STAGE_BYTES)

// ---------------- MMA for one K=64 stage ----------------
__device__ __forceinline__ void stage_mma(uint32_t sbase, uint32_t Aoff, uint32_t Boff,
                                          int am_base, int bn_base, int lane,
                                          float (&acc)[2][4][4])
{
    const int arow = ((lane >> 3) & 1) * 8 + (lane & 7);
    const int akb  = ((lane >> 4) & 1) * 16;
    const int brow = ((lane >> 4) & 1) * 8 + (lane & 7);
    const int bkb  = ((lane >> 3) & 1) * 16;
#pragma unroll
    for (int kk = 0; kk < 64; kk += 16) {
        uint32_t a0[4], a1[4], b0[4], b1[4];
        ldm4(a0, sbase + Aoff + SW128((am_base + arow) * 128 + kk * 2 + akb));
        ldm4(a1, sbase + Aoff + SW128((am_base + 16 + arow) * 128 + kk * 2 + akb));
        ldm4(b0, sbase + Boff + SW128((bn_base + brow) * 128 + kk * 2 + bkb));
        ldm4(b1, sbase + Boff + SW128((bn_base + 16 + brow) * 128 + kk * 2 + bkb));
        mma16816(acc[0][0], a0, b0[0], b0[1]);
        mma16816(acc[0][1], a0, b0[2], b0[3]);
        mma16816(acc[0][2], a0, b1[0], b1[1]);
        mma16816(acc[0][3], a0, b1[2], b1[3]);
        mma16816(acc[1][0], a1, b0[0], b0[1]);
        mma16816(acc[1][1], a1, b0[2], b0[3]);
        mma16816(acc[1][2], a1, b1[0], b1[1]);
        mma16816(acc[1][3], a1, b1[2], b1[3]);
    }
}

// ---------------- epilogues ----------------
// EPI 0: qkv transposed scatter -> bf16 (via smem). 1: out=e4+e5*acc. 2: gelu(bn)->bf16. 3: e4+e5*bn.
template <int EPI, typename OutT>
__device__ __forceinline__ void epi_frag(float (&acc)[2][4][4], char* smem,
                                         int m0, int n0, int wm, int wn, int lane, int t, int ldo,
                                         const float* __restrict__ e0, const float* __restrict__ e1,
                                         const float* __restrict__ e2, const float* __restrict__ e3,
                                         const float* __restrict__ e4, const float* __restrict__ e5,
                                         OutT* __restrict__ out)
{
    const int rIn = lane >> 2, cpair = (lane & 3) * 2;
    if (EPI == 0) {
        float* smf = (float*)smem;
        __syncthreads();
#pragma unroll
        for (int ni = 0; ni < 4; ni++) {
            const int cl = wn * 32 + ni * 8 + cpair;
#pragma unroll
            for (int mi = 0; mi < 2; mi++) {
#pragma unroll
                for (int h = 0; h < 2; h++) {
                    const int rl = wm * 32 + mi * 16 + rIn + h * 8;
                    smf[(cl + 0) * 132 + rl] = acc[mi][ni][2 * h + 0];
                    smf[(cl + 1) * 132 + rl] = acc[mi][ni][2 * h + 1];
                }
            }
        }
        __syncthreads();
        const int b = m0 / N_;
        const int nrow0 = (m0 - b * N_);
        const int rown = t & 63, seg = t >> 6;
        const int rr = n0 + rown;
        const int s = rr / C_, cc = rr - s * C_;
        bf16* dst = (bf16*)out + ((size_t)(s * B_ + b) * C_ + cc) * (size_t)N_ + nrow0 + seg * 32;
        const float* src = smf + rown * 132 + seg * 32;
#pragma unroll
        for (int i = 0; i < 8; i++) {
            float4 v = *(const float4*)(src + i * 4);
            __nv_bfloat162 p0 = __floats2bfloat162_rn(v.x, v.y);
            __nv_bfloat162 p1 = __floats2bfloat162_rn(v.z, v.w);
            uint2 u;
            u.x = *(uint32_t*)&p0;
            u.y = *(uint32_t*)&p1;
            *(uint2*)(dst + i * 4) = u;
        }
        return;
    }
#pragma unroll
    for (int ni = 0; ni < 4; ni++) {
        const int col = n0 + wn * 32 + ni * 8 + cpair;
        float s0 = 1.f, s1 = 1.f, bi0 = 0.f, bi1 = 0.f, g0 = 0.f, g1 = 0.f;
        if (EPI == 2 || EPI == 3) {
            s0 = e0[col + 0] * rsqrtf(e3[col + 0] + 1e-5f);
            s1 = e0[col + 1] * rsqrtf(e3[col + 1] + 1e-5f);
            bi0 = e1[col + 0] - e2[col + 0] * s0;
            bi1 = e1[col + 1] - e2[col + 1] * s1;
        }
        if (EPI == 1 || EPI == 3) { g0 = e5[col]; g1 = e5[col + 1]; }
#pragma unroll
        for (int mi = 0; mi < 2; mi++) {
#pragma unroll
            for (int h = 0; h < 2; h++) {
                const int row = m0 + wm * 32 + mi * 16 + rIn + h * 8;
                float a0 = acc[mi][ni][2 * h + 0];
                float a1 = acc[mi][ni][2 * h + 1];
                if (EPI == 2 || EPI == 3) { a0 = a0 * s0 + bi0; a1 = a1 * s1 + bi1; }
                if (EPI == 2) { a0 = gelu_f(a0); a1 = gelu_f(a1); }
                const size_t off = (size_t)row * ldo + col;
                if (EPI == 1 || EPI == 3) {
                    float2 xr = *(const float2*)(e4 + off);
                    a0 = xr.x + g0 * a0; a1 = xr.y + g1 * a1;
                }
                if (sizeof(OutT) == 2) {
                    __nv_bfloat162 p = __floats2bfloat162_rn(a0, a1);
                    *(uint32_t*)((bf16*)out + off) = *(uint32_t*)&p;
                } else {
                    *(float2*)((float*)out + off) = make_float2(a0, a1);
                }
            }
        }
    }
}

// ---------------- dense NT GEMM: D[128x64] = A[128xK] * Bw[64xK]^T, cp.async 3-stage ----------------
template <int EPI, typename OutT>
__global__ void __launch_bounds__(256, 2) tc_gemm(
    const bf16* __restrict__ A, const bf16* __restrict__ Bw, int K, int ldo,
    const float* __restrict__ e0, const float* __restrict__ e1,
    const float* __restrict__ e2, const float* __restrict__ e3,
    const float* __restrict__ e4, const float* __restrict__ e5,
    OutT* __restrict__ out)
{
    extern __shared__ char smem[];
    const int t = threadIdx.x, wid = t >> 5, lane = t & 31;
    const int m0 = blockIdx.x * 128, n0 = blockIdx.y * 64;
    const int wm = wid & 3, wn = wid >> 2;
    const uint32_t sbase = smem_u32(smem);
    const int q = t & 7, r0 = t >> 3;
    const int nc = K >> 6;

    float acc[2][4][4];
#pragma unroll
    for (int i = 0; i < 2; i++)
#pragma unroll
        for (int j = 0; j < 4; j++)
#pragma unroll
            for (int k = 0; k < 4; k++) acc[i][j][k] = 0.f;

    const char* Abase = (const char*)(A + (size_t)m0 * K);
    const char* Bbase = (const char*)(Bw + (size_t)n0 * K);
    const size_t rs = (size_t)K * 2;
    const uint32_t swA = SW128(r0 * 128 + q * 16);
    const uint32_t swA1 = SW128((r0 + 32) * 128 + q * 16);
    const uint32_t swA2 = SW128((r0 + 64) * 128 + q * 16);
    const uint32_t swA3 = SW128((r0 + 96) * 128 + q * 16);
    const uint32_t swB0 = SW128(r0 * 128 + q * 16);
    const uint32_t swB1 = SW128((r0 + 32) * 128 + q * 16);

    auto issue = [&](int c) {
        const uint32_t so = sbase + (uint32_t)(c % STAGES) * STAGE_BYTES;
        const size_t ko = (size_t)c * 128 + q * 16;
        cpa16(so + swA,  Abase + (size_t)(r0)      * rs + ko);
        cpa16(so + swA1, Abase + (size_t)(r0 + 32) * rs + ko);
        cpa16(so + swA2, Abase + (size_t)(r0 + 64) * rs + ko);
        cpa16(so + swA3, Abase + (size_t)(r0 + 96) * rs + ko);
        cpa16(so + 16384 + swB0, Bbase + (size_t)(r0)      * rs + ko);
        cpa16(so + 16384 + swB1, Bbase + (size_t)(r0 + 32) * rs + ko);
        CP_COMMIT();
    };

    for (int s = 0; s < STAGES - 1 && s < nc; s++) issue(s);
    for (int c = 0; c < nc; c++) {
        if (c + STAGES - 1 < nc) {
            asm volatile("cp.async.wait_group %0;" :: "n"(STAGES - 2) : "memory");
        } else {
            asm volatile("cp.async.wait_group 0;" ::: "memory");
        }
        __syncthreads();
        const uint32_t so = (uint32_t)(c % STAGES) * STAGE_BYTES;
        stage_mma(sbase, so, so + 16384, wm * 32, wn * 32, lane, acc);
        if (c + STAGES - 1 < nc) issue(c + STAGES - 1);
    }
    epi_frag<EPI, OutT>(acc, smem, m0, n0, wm, wn, lane, t, ldo, e0, e1, e2, e3, e4, e5, out);
}

// ---------------- 3x3 conv as 9-tap K-accumulated GEMM, cp.async 3-stage ----------------
template <int EPI, typename OutT>
__global__ void __launch_bounds__(256, 2) tc_conv(
    const bf16* __restrict__ A, const bf16* __restrict__ Wt,
    const float* __restrict__ e0, const float* __restrict__ e1,
    const float* __restrict__ e2, const float* __restrict__ e3,
    const float* __restrict__ e4, const float* __restrict__ e5,
    OutT* __restrict__ out)
{
    extern __shared__ char smem[];
    const int t = threadIdx.x, wid = t >> 5, lane = t & 31;
    const int m0 = blockIdx.x * 128, n0 = blockIdx.y * 64;
    const int wm = wid & 3, wn = wid >> 2;
    const uint32_t sbase = smem_u32(smem);
    const int q = t & 7, r0 = t >> 3;

    const int m0p = m0 % N_;
    int hh[4], ww[4];
#pragma unroll
    for (int it = 0; it < 4; it++) {
        int p = m0p + r0 + it * 32;
        hh[it] = p / WW_;
        ww[it] = p - hh[it] * WW_;
    }
    uint32_t swA[4], swB[2];
#pragma unroll
    for (int it = 0; it < 4; it++) swA[it] = SW128((r0 + it * 32) * 128 + q * 16);
#pragma unroll
    for (int it = 0; it < 2; it++) swB[it] = SW128((r0 + it * 32) * 128 + q * 16);

    float acc[2][4][4];
#pragma unroll
    for (int i = 0; i < 2; i++)
#pragma unroll
        for (int j = 0; j < 4; j++)
#pragma unroll
            for (int k = 0; k < 4; k++) acc[i][j][k] = 0.f;

    auto issue = [&](int c) {
        const int tap = c / 6, kc = c - tap * 6;
        const int dy = tap / 3 - 1, dx = tap % 3 - 1;
        const uint32_t so = sbase + (uint32_t)(c % STAGES) * STAGE_BYTES;
        const bf16* Atap = A + (size_t)(m0 + dy * WW_ + dx) * C_ + kc * 64;
        const bf16* Wtap = Wt + (size_t)tap * C_ * C_ + (size_t)n0 * C_ + kc * 64;
#pragma unroll
        for (int it = 0; it < 4; it++) {
            bool ok = ((unsigned)(hh[it] + dy) < (unsigned)HH_) &&
                      ((unsigned)(ww[it] + dx) < (unsigned)WW_);
            cpa16z(so + swA[it], (const char*)(Atap + (size_t)(r0 + it * 32) * C_) + q * 16, ok);
        }
#pragma unroll
        for (int it = 0; it < 2; it++)
            cpa16(so + 16384 + swB[it], (const char*)(Wtap + (size_t)(r0 + it * 32) * C_) + q * 16);
        CP_COMMIT();
    };

    const int nc = 54;
    for (int s = 0; s < STAGES - 1; s++) issue(s);
    for (int c = 0; c < nc; c++) {
        if (c + STAGES - 1 < nc) {
            asm volatile("cp.async.wait_group %0;" :: "n"(STAGES - 2) : "memory");
        } else {
            asm volatile("cp.async.wait_group 0;" ::: "memory");
        }
        __syncthreads();
        const uint32_t so = (uint32_t)(c % STAGES) * STAGE_BYTES;
        stage_mma(sbase, so, so + 16384, wm * 32, wn * 32, lane, acc);
        if (c + STAGES - 1 < nc) issue(c + STAGES - 1);
    }
    epi_frag<EPI, OutT>(acc, smem, m0, n0, wm, wn, lane, t, C_, e0, e1, e2, e3, e4, e5, out);
}

// ---------------- LayerNorm -> bf16 ----------------
__global__ void ln_kernel(const float* __restrict__ in, const float* __restrict__ g,
                          const float* __restrict__ b, bf16* __restrict__ outp)
{
    const int r = blockIdx.x;
    const int t = threadIdx.x;
    const float* row = in + (size_t)r * C_;
    float v0 = row[t], v1 = row[t + 128], v2 = row[t + 256];
    float s = v0 + v1 + v2;
    float ss = v0 * v0 + v1 * v1 + v2 * v2;
    for (int o = 16; o; o >>= 1) {
        s  += __shfl_down_sync(0xffffffffu, s,  o);
        ss += __shfl_down_sync(0xffffffffu, ss, o);
    }
    __shared__ float sh[8];
    if ((t & 31) == 0) { sh[t >> 5] = s; sh[4 + (t >> 5)] = ss; }
    __syncthreads();
    if (t == 0) {
        float S  = sh[0] + sh[1] + sh[2] + sh[3];
        float SS = sh[4] + sh[5] + sh[6] + sh[7];
        float mean = S * (1.0f / C_);
        float var  = SS * (1.0f / C_) - mean * mean;
        sh[0] = mean;
        sh[1] = rsqrtf(var + 1e-5f);
    }
    __syncthreads();
    float mean = sh[0], rstd = sh[1];
    bf16* orow = outp + (size_t)r * C_;
    orow[t]       = __float2bfloat16_rn((v0 - mean) * rstd * g[t]       + b[t]);
    orow[t + 128] = __float2bfloat16_rn((v1 - mean) * rstd * g[t + 128] + b[t + 128]);
    orow[t + 256] = __float2bfloat16_rn((v2 - mean) * rstd * g[t + 256] + b[t + 256]);
}

// ---------------- conversions ----------------
__global__ void f2bf(const float* __restrict__ in, bf16* __restrict__ outp, int n)
{
    int i = blockIdx.x * 256 + threadIdx.x;
    if (i < n) outp[i] = __float2bfloat16_rn(in[i]);
}
__global__ void wtrans_bf(const float* __restrict__ w, bf16* __restrict__ wt)
{
    int i = blockIdx.x * 256 + threadIdx.x;
    if (i >= 9 * C_ * C_) return;
    int tap = i / (C_ * C_);
    int rem = i - tap * (C_ * C_);
    int o = rem / C_, ci = rem - o * C_;
    wt[i] = __float2bfloat16_rn(w[(size_t)(o * C_ + ci) * 9 + tap]);
}

// ---------------- attention small kernels (bf16 qkvT) ----------------
__global__ void rnorm_kernel()
{
    const int row = blockIdx.x;
    const bf16* base = g_qkvT + (size_t)row * N_;
    int t = threadIdx.x;
    float ss = 0.f;
    for (int i = t; i < N_ / 8; i += 256) {
        uint4 u = *(const uint4*)(base + i * 8);
        const __nv_bfloat162* p = (const __nv_bfloat162*)&u;
#pragma unroll
        for (int j = 0; j < 4; j++) {
            float2 f = __bfloat1622float2(p[j]);
            ss += f.x * f.x + f.y * f.y;
        }
    }
    for (int o = 16; o; o >>= 1) ss += __shfl_down_sync(0xffffffffu, ss, o);
    __shared__ float sh[8];
    if ((t & 31) == 0) sh[t >> 5] = ss;
    __syncthreads();
    if (t == 0) {
        float S = sh[0] + sh[1] + sh[2] + sh[3] + sh[4] + sh[5] + sh[6] + sh[7];
        g_rn[row] = 1.0f / fmaxf(sqrtf(S), 1e-12f);
    }
}

__global__ void attn_qk(const float* __restrict__ temp)
{
    const int bh = blockIdx.x;
    const int b = bh >> 3, h = bh & 7;
    __shared__ float qs[DD_ * 65];
    __shared__ float ks[DD_ * 65];
    const int t = threadIdx.x;
    const bf16* qbase = g_qkvT + ((size_t)(b)      * C_ + h * DD_) * N_;
    const bf16* kbase = g_qkvT + ((size_t)(B_ + b) * C_ + h * DD_) * N_;
    float acc[3][3] = {};
    const int d0 = (t >> 4) * 3, e0i = (t & 15) * 3;
    for (int n0 = 0; n0 < N_; n0 += 64) {
        __syncthreads();
        for (int idx = t; idx < DD_ * 32; idx += 256) {
            int d = idx >> 5, nn2 = (idx & 31) * 2;
            float2 qf = __bfloat1622float2(*(const __nv_bfloat162*)(qbase + (size_t)d * N_ + n0 + nn2));
            float2 kf = __bfloat1622float2(*(const __nv_bfloat162*)(kbase + (size_t)d * N_ + n0 + nn2));
            qs[d * 65 + nn2] = qf.x; qs[d * 65 + nn2 + 1] = qf.y;
            ks[d * 65 + nn2] = kf.x; ks[d * 65 + nn2 + 1] = kf.y;
        }
        __syncthreads();
#pragma unroll 4
        for (int nn = 0; nn < 64; nn++) {
            float q0 = qs[d0 * 65 + nn], q1 = qs[(d0 + 1) * 65 + nn], q2 = qs[(d0 + 2) * 65 + nn];
            float k0 = ks[e0i * 65 + nn], k1 = ks[(e0i + 1) * 65 + nn], k2 = ks[(e0i + 2) * 65 + nn];
            acc[0][0] += q0 * k0; acc[0][1] += q0 * k1; acc[0][2] += q0 * k2;
            acc[1][0] += q1 * k0; acc[1][1] += q1 * k1; acc[1][2] += q1 * k2;
            acc[2][0] += q2 * k0; acc[2][1] += q2 * k1; acc[2][2] += q2 * k2;
        }
    }
    const float tp = temp[h];
#pragma unroll
    for (int i = 0; i < 3; i++) {
        float rq = g_rn[b * C_ + h * DD_ + d0 + i];
#pragma unroll
        for (int j = 0; j < 3; j++) {
            float rk = g_rn[B_ * C_ + b * C_ + h * DD_ + e0i + j];
            g_attn[((size_t)bh * DD_ + d0 + i) * DD_ + e0i + j] = acc[i][j] * rq * rk * tp;
        }
    }
}

__global__ void softmax48()
{
    int row = blockIdx.x * blockDim.x + threadIdx.x;
    if (row >= B_ * NH_ * DD_) return;
    float* p = g_attn + (size_t)row * DD_;
    float mx = -1e30f;
#pragma unroll
    for (int i = 0; i < DD_; i++) mx = fmaxf(mx, p[i]);
    float s = 0.f;
#pragma unroll
    for (int i = 0; i < DD_; i++) { float e = expf(p[i] - mx); p[i] = e; s += e; }
    float r = 1.0f / s;
#pragma unroll
    for (int i = 0; i < DD_; i++) p[i] *= r;
}

__global__ void attn_v()
{
    const int nt = blockIdx.x;
    const int bh = blockIdx.y;
    const int b = bh >> 3, h = bh & 7;
    __shared__ float P[DD_ * DD_];
    __shared__ float vs[DD_ * 132];
    const int t = threadIdx.x;
    for (int idx = t; idx < DD_ * DD_; idx += 256) P[idx] = g_attn[(size_t)bh * DD_ * DD_ + idx];
    const bf16* vbase = g_qkvT + ((size_t)(2 * B_ + b) * C_ + h * DD_) * N_ + nt * 128;
    for (int idx = t; idx < DD_ * 64; idx += 256) {
        int e = idx >> 6, nn2 = (idx & 63) * 2;
        float2 vf = __bfloat1622float2(*(const __nv_bfloat162*)(vbase + (size_t)e * N_ + nn2));
        vs[e * 132 + nn2] = vf.x;
        vs[e * 132 + nn2 + 1] = vf.y;
    }
    __syncthreads();
    const int ng = t & 31, dg = t >> 5;
    const int n = ng * 4, dd0 = dg * 6;
    float acc[6][4] = {};
#pragma unroll 4
    for (int e = 0; e < DD_; e++) {
        float4 v4 = *(const float4*)&vs[e * 132 + n];
#pragma unroll
        for (int i = 0; i < 6; i++) {
            float pv = P[(dd0 + i) * DD_ + e];
            acc[i][0] += pv * v4.x; acc[i][1] += pv * v4.y;
            acc[i][2] += pv * v4.z; acc[i][3] += pv * v4.w;
        }
    }
    size_t mbase = ((size_t)b * N_ + nt * 128 + n) * C_ + h * DD_ + dd0;
#pragma unroll
    for (int i = 0; i < 6; i++)
#pragma unroll
        for (int jj = 0; jj < 4; jj++)
            g_oncb[mbase + i + (size_t)jj * C_] = __float2bfloat16_rn(acc[i][jj]);
}

__global__ void tail_kernel(float* o, const int* pH, const int* pW, int extra)
{
    int i = threadIdx.x;
    if (i < extra) {
        float v = 0.f;
        if (i == 0) v = (float)(*pH);
        if (i == 1) v = (float)(*pW);
        o[(size_t)ROWS_ * C_ + i] = v;
    }
}

extern "C" void kernel_launch(void* const* d_in, const int* in_sizes, int n_in,
                              void* d_out, int out_size)
{
    const float* x      = (const float*)d_in[0];
    const float* ln1_g  = (const float*)d_in[1];
    const float* ln1_b  = (const float*)d_in[2];
    const float* w_qkv  = (const float*)d_in[3];
    const float* temp   = (const float*)d_in[4];
    const float* w_proj = (const float*)d_in[5];
    const float* gamma1 = (const float*)d_in[6];
    const float* ln2_g  = (const float*)d_in[7];
    const float* ln2_b  = (const float*)d_in[8];
    const float* mlp_w1 = (const float*)d_in[9];
    const float* bn1_g  = (const float*)d_in[10];
    const float* bn1_b  = (const float*)d_in[11];
    const float* bn1_m  = (const float*)d_in[12];
    const float* bn1_v  = (const float*)d_in[13];
    const float* mlp_w2 = (const float*)d_in[14];
    const float* bn2_g  = (const float*)d_in[15];
    const float* bn2_b  = (const float*)d_in[16];
    const float* bn2_m  = (const float*)d_in[17];
    const float* bn2_v  = (const float*)d_in[18];
    const float* gamma2 = (const float*)d_in[19];
    const float* ln3_g  = (const float*)d_in[20];
    const float* ln3_b  = (const float*)d_in[21];
    const float* pconv1 = (const float*)d_in[22];
    const float* pbn_g  = (const float*)d_in[23];
    const float* pbn_b  = (const float*)d_in[24];
    const float* pbn_m  = (const float*)d_in[25];
    const float* pbn_v  = (const float*)d_in[26];
    const float* pconv2 = (const float*)d_in[27];
    const float* gamma3 = (const float*)d_in[28];
    const int*   pH     = (const int*)d_in[29];
    const int*   pW     = (const int*)d_in[30];
    float* dout = (float*)d_out;

    bf16 *xnb, *qkvT, *oncb, *hidb, *c1b, *wqkvb, *wprojb, *w1b, *w2b, *wt1b, *wt2b;
    float *x1, *x2;
    cudaGetSymbolAddress((void**)&xnb,    g_xnb);
    cudaGetSymbolAddress((void**)&qkvT,   g_qkvT);
    cudaGetSymbolAddress((void**)&oncb,   g_oncb);
    cudaGetSymbolAddress((void**)&x1,     g_x1);
    cudaGetSymbolAddress((void**)&hidb,   g_hidb);
    cudaGetSymbolAddress((void**)&x2,     g_x2);
    cudaGetSymbolAddress((void**)&c1b,    g_c1b);
    cudaGetSymbolAddress((void**)&wqkvb,  g_wqkvb);
    cudaGetSymbolAddress((void**)&wprojb, g_wprojb);
    cudaGetSymbolAddress((void**)&w1b,    g_w1b);
    cudaGetSymbolAddress((void**)&w2b,    g_w2b);
    cudaGetSymbolAddress((void**)&wt1b,   g_wt1b);
    cudaGetSymbolAddress((void**)&wt2b,   g_wt2b);

    cudaFuncSetAttribute((const void*)tc_gemm<0, bf16>,  cudaFuncAttributeMaxDynamicSharedMemorySize, SMEM_BYTES);
    cudaFuncSetAttribute((const void*)tc_gemm<1, float>, cudaFuncAttributeMaxDynamicSharedMemorySize, SMEM_BYTES);
    cudaFuncSetAttribute((const void*)tc_gemm<2, bf16>,  cudaFuncAttributeMaxDynamicSharedMemorySize, SMEM_BYTES);
    cudaFuncSetAttribute((const void*)tc_gemm<3, float>, cudaFuncAttributeMaxDynamicSharedMemorySize, SMEM_BYTES);
    cudaFuncSetAttribute((const void*)tc_conv<2, bf16>,  cudaFuncAttributeMaxDynamicSharedMemorySize, SMEM_BYTES);
    cudaFuncSetAttribute((const void*)tc_conv<1, float>, cudaFuncAttributeMaxDynamicSharedMemorySize, SMEM_BYTES);

    const float* np = nullptr;

    // weight conversions
    f2bf<<<(3 * C_ * C_ + 255) / 256, 256>>>(w_qkv, wqkvb, 3 * C_ * C_);
    f2bf<<<(C_ * C_ + 255) / 256, 256>>>(w_proj, wprojb, C_ * C_);
    f2bf<<<(C2_ * C_ + 255) / 256, 256>>>(mlp_w1, w1b, C2_ * C_);
    f2bf<<<(C_ * C2_ + 255) / 256, 256>>>(mlp_w2, w2b, C_ * C2_);
    wtrans_bf<<<(9 * C_ * C_ + 255) / 256, 256>>>(pconv1, wt1b);
    wtrans_bf<<<(9 * C_ * C_ + 255) / 256, 256>>>(pconv2, wt2b);

    // --- attention block ---
    ln_kernel<<<ROWS_, 128>>>(x, ln1_g, ln1_b, xnb);
    tc_gemm<0, bf16><<<dim3(288, 18), 256, SMEM_BYTES>>>(xnb, wqkvb, C_, 0, np, np, np, np, np, np, qkvT);
    rnorm_kernel<<<2 * B_ * C_, 256>>>();
    attn_qk<<<B_ * NH_, 256>>>(temp);
    softmax48<<<(B_ * NH_ * DD_ + 255) / 256, 256>>>();
    attn_v<<<dim3(18, B_ * NH_), 256>>>();
    tc_gemm<1, float><<<dim3(288, 6), 256, SMEM_BYTES>>>(oncb, wprojb, C_, C_, np, np, np, np, x, gamma1, x1);

    // --- ConvMlp block ---
    ln_kernel<<<ROWS_, 128>>>(x1, ln2_g, ln2_b, xnb);
    tc_gemm<2, bf16><<<dim3(288, 12), 256, SMEM_BYTES>>>(xnb, w1b, C_, C2_, bn1_g, bn1_b, bn1_m, bn1_v, np, np, hidb);
    tc_gemm<3, float><<<dim3(288, 6), 256, SMEM_BYTES>>>(hidb, w2b, C2_, C_, bn2_g, bn2_b, bn2_m, bn2_v, x1, gamma2, x2);

    // --- projection block (3x3 convs) ---
    ln_kernel<<<ROWS_, 128>>>(x2, ln3_g, ln3_b, xnb);
    tc_conv<2, bf16><<<dim3(288, 6), 256, SMEM_BYTES>>>(xnb, wt1b, pbn_g, pbn_b, pbn_m, pbn_v, np, np, c1b);
    tc_conv<1, float><<<dim3(288, 6), 256, SMEM_BYTES>>>(c1b, wt2b, np, np, np, np, x2, gamma3, dout);

    int extra = out_size - (int)((size_t)ROWS_ * C_);
    if (extra > 0) tail_kernel<<<1, 32>>>(dout, pH, pW, extra);
}